// round 1
// baseline (speedup 1.0000x reference)
#include <cuda_runtime.h>
#include <math.h>
#include <stdint.h>

// ---------------------------------------------------------------------------
// Problem constants
// ---------------------------------------------------------------------------
constexpr long BB    = 16;
constexpr long LL    = 512;
constexpr long MTOK  = BB * LL;      // 8192 tokens
constexpr long DMODEL= 256;
constexpr long DIN   = 128;
constexpr long DINNER= 256;
constexpr long NST   = 16;           // state size N
constexpr long KCONV = 4;
constexpr long RR    = 8;
constexpr long NL    = 12;
constexpr long DFF   = 1024;

// ---------------------------------------------------------------------------
// Scratch arena (one __device__ global, allocation-free)
// ---------------------------------------------------------------------------
constexpr long OFF_X    = 0;
constexpr long OFF_LN   = OFF_X    + MTOK * 256;
constexpr long OFF_B256 = OFF_LN   + MTOK * 256;
constexpr long OFF_U    = OFF_B256 + MTOK * 256;
constexpr long OFF_XZ   = OFF_U    + 2 * MTOK * 128;
constexpr long OFF_XC   = OFF_XZ   + 2 * MTOK * 512;
constexpr long OFF_DBC  = OFF_XC   + 2 * MTOK * 256;
constexpr long OFF_DT   = OFF_DBC  + 2 * MTOK * 40;
constexpr long OFF_Y    = OFF_DT   + 2 * MTOK * 256;
constexpr long OFF_SO   = OFF_Y    + 2 * MTOK * 256;
constexpr long OFF_CAT  = OFF_SO   + 2 * MTOK * 128;
constexpr long OFF_FF   = OFF_CAT  + MTOK * 256;
constexpr long TOTAL_F  = OFF_FF   + MTOK * 1024;

__device__ float g_buf[TOTAL_F];

// ---------------------------------------------------------------------------
// Block-wide sum over 256 threads
// ---------------------------------------------------------------------------
__device__ __forceinline__ float blockSum256(float v, float* sbuf)
{
#pragma unroll
    for (int o = 16; o > 0; o >>= 1)
        v += __shfl_xor_sync(0xffffffffu, v, o);
    __syncthreads();                       // protect sbuf re-use across calls
    if ((threadIdx.x & 31) == 0) sbuf[threadIdx.x >> 5] = v;
    __syncthreads();
    float s = sbuf[0];
#pragma unroll
    for (int i = 1; i < 8; i++) s += sbuf[i];
    return s;
}

// ---------------------------------------------------------------------------
// Embedding: x = LN(ids @ proj_w + proj_b)
// one block per token, 256 threads (one per output channel)
// ---------------------------------------------------------------------------
__global__ void embed_ln_kernel(const float* __restrict__ ids,
                                const float* __restrict__ pw,
                                const float* __restrict__ pb,
                                const float* __restrict__ gam,
                                const float* __restrict__ bet,
                                float* __restrict__ x)
{
    __shared__ float sin[32];
    __shared__ float sred[8];
    int m = blockIdx.x, d = threadIdx.x;
    if (d < 32) sin[d] = ids[(long)m * 32 + d];
    __syncthreads();
    float v = pb[d];
#pragma unroll
    for (int e = 0; e < 32; e++)
        v = fmaf(sin[e], pw[e * 256 + d], v);
    float mean = blockSum256(v, sred) * (1.f / 256.f);
    float c = v - mean;
    float var = blockSum256(c * c, sred) * (1.f / 256.f);
    x[(long)m * 256 + d] = c * rsqrtf(var + 1e-5f) * gam[d] + bet[d];
}

// ---------------------------------------------------------------------------
// LayerNorm over D=256, optional residual add: out = LN(in [+ res])
// ---------------------------------------------------------------------------
__global__ void ln_kernel(const float* __restrict__ in,
                          const float* __restrict__ res,
                          const float* __restrict__ gam,
                          const float* __restrict__ bet,
                          float* __restrict__ out)
{
    __shared__ float sred[8];
    int m = blockIdx.x, d = threadIdx.x;
    float v = in[(long)m * 256 + d];
    if (res) v += res[(long)m * 256 + d];
    float mean = blockSum256(v, sred) * (1.f / 256.f);
    float c = v - mean;
    float var = blockSum256(c * c, sred) * (1.f / 256.f);
    out[(long)m * 256 + d] = c * rsqrtf(var + 1e-5f) * gam[d] + bet[d];
}

// ---------------------------------------------------------------------------
// Generic batched SGEMM: C[g] = A[g] @ W[g] (+ bias[g])
// A: [M, K] row-major with leading dim lda; W: [K, N] row-major; C: [M, N].
// Tile 128x64, BK=16, 256 threads, 8x4 micro-tile.
// ---------------------------------------------------------------------------
__global__ void sgemm_kernel(const float* __restrict__ A,
                             const float* __restrict__ W,
                             const float* __restrict__ bias,
                             float* __restrict__ C,
                             int M, int N, int K, int lda,
                             long sAg, long sWg, long sCg, long sBg)
{
    int g = blockIdx.z;
    A += (long)g * sAg;
    W += (long)g * sWg;
    C += (long)g * sCg;
    if (bias) bias += (long)g * sBg;

    __shared__ __align__(16) float As[16][128];
    __shared__ __align__(16) float Ws[16][64];

    int tid = threadIdx.x;
    int tx = tid & 15;        // 0..15 -> column group (4 cols)
    int ty = tid >> 4;        // 0..15 -> row group (8 rows)
    int rowBase = blockIdx.y * 128;
    int colBase = blockIdx.x * 64;

    float acc[8][4];
#pragma unroll
    for (int i = 0; i < 8; i++)
#pragma unroll
        for (int j = 0; j < 4; j++) acc[i][j] = 0.f;

    for (int k0 = 0; k0 < K; k0 += 16) {
        // load A tile (128 x 16), transposed into As[k][m]
#pragma unroll
        for (int it = 0; it < 8; it++) {
            int idx = tid + it * 256;
            int m = idx >> 4;
            int kk = idx & 15;
            int gr = rowBase + m, gk = k0 + kk;
            As[kk][m] = (gr < M && gk < K) ? A[(long)gr * lda + gk] : 0.f;
        }
        // load W tile (16 x 64)
#pragma unroll
        for (int it = 0; it < 4; it++) {
            int idx = tid + it * 256;
            int kk = idx >> 6;
            int n = idx & 63;
            int gk = k0 + kk, gn = colBase + n;
            Ws[kk][n] = (gk < K && gn < N) ? W[(long)gk * N + gn] : 0.f;
        }
        __syncthreads();
#pragma unroll
        for (int k = 0; k < 16; k++) {
            float a[8], w[4];
            float4 a0 = *(const float4*)&As[k][ty * 8];
            float4 a1 = *(const float4*)&As[k][ty * 8 + 4];
            a[0] = a0.x; a[1] = a0.y; a[2] = a0.z; a[3] = a0.w;
            a[4] = a1.x; a[5] = a1.y; a[6] = a1.z; a[7] = a1.w;
            float4 w0 = *(const float4*)&Ws[k][tx * 4];
            w[0] = w0.x; w[1] = w0.y; w[2] = w0.z; w[3] = w0.w;
#pragma unroll
            for (int i = 0; i < 8; i++)
#pragma unroll
                for (int j = 0; j < 4; j++)
                    acc[i][j] = fmaf(a[i], w[j], acc[i][j]);
        }
        __syncthreads();
    }

#pragma unroll
    for (int i = 0; i < 8; i++) {
        int gr = rowBase + ty * 8 + i;
        if (gr >= M) continue;
#pragma unroll
        for (int j = 0; j < 4; j++) {
            int gn = colBase + tx * 4 + j;
            if (gn >= N) continue;
            float v = acc[i][j];
            if (bias) v += bias[gn];
            C[(long)gr * N + gn] = v;
        }
    }
}

// ---------------------------------------------------------------------------
// split + reverse: h [M,256] -> u[0][m][0:128]=h[:, :128];
//                              u[1][b, L-1-t][:] = h[b,t,128:]
// ---------------------------------------------------------------------------
__global__ void splitrev_kernel(const float* __restrict__ h, float* __restrict__ u)
{
    long i = (long)blockIdx.x * 256 + threadIdx.x;   // over M*256
    if (i >= MTOK * 256) return;
    long m = i >> 8;
    int j = (int)(i & 255);
    float v = h[i];
    if (j < 128) {
        u[m * 128 + j] = v;
    } else {
        long b = m >> 9;
        long t = m & 511;
        u[MTOK * 128 + ((b << 9) + 511 - t) * 128 + (j - 128)] = v;
    }
}

// ---------------------------------------------------------------------------
// depthwise causal conv (K=4) + bias + silu on the x-half of xz
// xz: [2][M][512] (x = cols 0..255, z = cols 256..511) -> xc [2][M][256]
// ---------------------------------------------------------------------------
__global__ void conv_silu_kernel(const float* __restrict__ xz,
                                 const float* __restrict__ convw,
                                 const float* __restrict__ convb,
                                 float* __restrict__ xc)
{
    long i = (long)blockIdx.x * 256 + threadIdx.x;   // over 2*M*256
    if (i >= 2 * MTOK * 256) return;
    int d = (int)(i & 255);
    long gm = i >> 8;
    int g = (int)(gm / MTOK);
    long m = gm % MTOK;
    int t = (int)(m & 511);

    const float* w = convw + ((long)g * 256 + d) * 4;
    const float* xp = xz + ((long)g * MTOK + m) * 512 + d;
    float acc = convb[(long)g * 256 + d];
#pragma unroll
    for (int k = 0; k < 4; k++) {
        int tt = t - 3 + k;
        if (tt >= 0) acc = fmaf(xp[(long)(k - 3) * 512], w[k], acc);
    }
    xc[i] = acc / (1.f + expf(-acc));   // silu
}

// ---------------------------------------------------------------------------
// in-place softplus
// ---------------------------------------------------------------------------
__global__ void softplus_kernel(float* __restrict__ buf, long n)
{
    long i = (long)blockIdx.x * 256 + threadIdx.x;
    if (i >= n) return;
    float v = buf[i];
    buf[i] = (v > 20.f) ? v : log1pf(expf(v));
}

// ---------------------------------------------------------------------------
// Selective scan. One 16-lane sub-warp group per (g, b, d) channel; lane = n.
// h_t = exp(dt*A_n) * h_{t-1} + dt * B_n * x ;  y_t = sum_n h_t * C_n + D*x
// ---------------------------------------------------------------------------
__global__ void scan_kernel(const float* __restrict__ dt,
                            const float* __restrict__ xc,
                            const float* __restrict__ dbc,
                            const float* __restrict__ alog,   // [2][256][16] (layer slice)
                            const float* __restrict__ dpar,   // [2][256]
                            float* __restrict__ y)
{
    int grp = blockIdx.x * 16 + (threadIdx.x >> 4);   // 0 .. 8191
    int n = threadIdx.x & 15;
    int g = grp >> 12;
    int bd = grp & 4095;
    int b = bd >> 8;
    int d = bd & 255;

    float A = -expf(alog[((long)(g * 256 + d)) * 16 + n]);
    float dp = dpar[(long)g * 256 + d];

    long mbase = (long)g * MTOK + (long)b * 512;
    const float* dtp = dt + mbase * 256 + d;
    const float* xcp = xc + mbase * 256 + d;
    const float* dbp = dbc + mbase * 40;
    float* yp = y + mbase * 256 + d;

    float h = 0.f;
    for (int t = 0; t < 512; t++) {
        float dtv = dtp[(long)t * 256];
        float xv = xcp[(long)t * 256];
        float Bn = dbp[(long)t * 40 + 8 + n];
        float Cn = dbp[(long)t * 40 + 24 + n];
        h = expf(dtv * A) * h + dtv * Bn * xv;
        float p = h * Cn;
        p += __shfl_xor_sync(0xffffffffu, p, 8);
        p += __shfl_xor_sync(0xffffffffu, p, 4);
        p += __shfl_xor_sync(0xffffffffu, p, 2);
        p += __shfl_xor_sync(0xffffffffu, p, 1);
        if (n == 0) yp[(long)t * 256] = p + dp * xv;
    }
}

// ---------------------------------------------------------------------------
// y *= silu(z)    (z = xz[..., 256:512])
// ---------------------------------------------------------------------------
__global__ void ygate_kernel(float* __restrict__ y, const float* __restrict__ xz)
{
    long i = (long)blockIdx.x * 256 + threadIdx.x;   // over 2*M*256
    if (i >= 2 * MTOK * 256) return;
    int d = (int)(i & 255);
    long gm = i >> 8;
    float z = xz[gm * 512 + 256 + d];
    y[i] *= z / (1.f + expf(-z));
}

// ---------------------------------------------------------------------------
// concat + un-reverse: cat[m][0:128]=so0[m]; cat[b,t][128:]=so1[b, L-1-t]
// ---------------------------------------------------------------------------
__global__ void concat_kernel(const float* __restrict__ so, float* __restrict__ cat)
{
    long i = (long)blockIdx.x * 256 + threadIdx.x;   // over M*256 (output index)
    if (i >= MTOK * 256) return;
    long m = i >> 8;
    int j = (int)(i & 255);
    float v;
    if (j < 128) {
        v = so[m * 128 + j];
    } else {
        long b = m >> 9;
        long t = m & 511;
        v = so[MTOK * 128 + ((b << 9) + 511 - t) * 128 + (j - 128)];
    }
    cat[i] = v;
}

// ---------------------------------------------------------------------------
// in-place exact GELU
// ---------------------------------------------------------------------------
__global__ void gelu_kernel(float* __restrict__ buf, long n)
{
    long i = (long)blockIdx.x * 256 + threadIdx.x;
    if (i >= n) return;
    float v = buf[i];
    buf[i] = 0.5f * v * (1.f + erff(v * 0.70710678118654752f));
}

// ---------------------------------------------------------------------------
// Host-side launcher helpers
// ---------------------------------------------------------------------------
static void launch_sgemm(const float* A, const float* W, const float* bias, float* C,
                         int M, int N, int K, int lda, int G,
                         long sAg, long sWg, long sCg, long sBg)
{
    dim3 grid((N + 63) / 64, (M + 127) / 128, G);
    sgemm_kernel<<<grid, 256>>>(A, W, bias, C, M, N, K, lda, sAg, sWg, sCg, sBg);
}

extern "C" void kernel_launch(void* const* d_in, const int* in_sizes, int n_in,
                              void* d_out, int out_size)
{
    const float* input_ids = (const float*)d_in[0];
    const float* proj_w    = (const float*)d_in[1];
    const float* proj_b    = (const float*)d_in[2];
    const float* ln0_g     = (const float*)d_in[3];
    const float* ln0_b     = (const float*)d_in[4];
    const float* ln1_g     = (const float*)d_in[5];
    const float* ln1_b     = (const float*)d_in[6];
    const float* ip_w      = (const float*)d_in[7];
    const float* ip_b      = (const float*)d_in[8];
    const float* s_inw     = (const float*)d_in[9];
    const float* s_convw   = (const float*)d_in[10];
    const float* s_convb   = (const float*)d_in[11];
    const float* s_xw      = (const float*)d_in[12];
    const float* s_dtw     = (const float*)d_in[13];
    const float* s_dtb     = (const float*)d_in[14];
    const float* s_alog    = (const float*)d_in[15];
    const float* s_d       = (const float*)d_in[16];
    const float* s_outw    = (const float*)d_in[17];
    const float* op_w      = (const float*)d_in[18];
    const float* op_b      = (const float*)d_in[19];
    const float* ln2_g     = (const float*)d_in[20];
    const float* ln2_b     = (const float*)d_in[21];
    const float* f_w1      = (const float*)d_in[22];
    const float* f_b1      = (const float*)d_in[23];
    const float* f_w2      = (const float*)d_in[24];
    const float* f_b2      = (const float*)d_in[25];
    const float* ln3_g     = (const float*)d_in[26];
    const float* ln3_b     = (const float*)d_in[27];

    float* base = nullptr;
    cudaGetSymbolAddress((void**)&base, g_buf);

    float* X    = base + OFF_X;
    float* LNb  = base + OFF_LN;
    float* B256 = base + OFF_B256;
    float* U    = base + OFF_U;
    float* XZ   = base + OFF_XZ;
    float* XC   = base + OFF_XC;
    float* DBC  = base + OFF_DBC;
    float* DT   = base + OFF_DT;
    float* Y    = base + OFF_Y;
    float* SO   = base + OFF_SO;
    float* CAT  = base + OFF_CAT;
    float* FF   = base + OFF_FF;

    const int M = (int)MTOK;
    const long EW2 = 2 * MTOK * 256;   // big elementwise extent
    const int EW2_BLOCKS = (int)((EW2 + 255) / 256);
    const int EW1_BLOCKS = (int)((MTOK * 256 + 255) / 256);

    // embed + LN0
    embed_ln_kernel<<<M, 256>>>(input_ids, proj_w, proj_b, ln0_g, ln0_b, X);

    for (int l = 0; l < 12; l++) {
        // 1. LN1
        ln_kernel<<<M, 256>>>(X, nullptr, ln1_g + l * 256, ln1_b + l * 256, LNb);
        // 2. in-proj h = LN @ ip_w + ip_b   [M,256]
        launch_sgemm(LNb, ip_w + (long)l * 256 * 256, ip_b + l * 256, B256,
                     M, 256, 256, 256, 1, 0, 0, 0, 0);
        // 3. split fwd / reversed bwd -> U [2][M][128]
        splitrev_kernel<<<EW1_BLOCKS, 256>>>(B256, U);
        // 4. xz = u @ inw   [2][M][512]
        launch_sgemm(U, s_inw + (long)l * 2 * 128 * 512, nullptr, XZ,
                     M, 512, 128, 128, 2, MTOK * 128, 128 * 512, MTOK * 512, 0);
        // 5. depthwise conv + silu -> XC [2][M][256]
        conv_silu_kernel<<<EW2_BLOCKS, 256>>>(XZ, s_convw + (long)l * 2 * 256 * 4,
                                              s_convb + (long)l * 2 * 256, XC);
        // 6. dbc = xc @ xw  [2][M][40]
        launch_sgemm(XC, s_xw + (long)l * 2 * 256 * 40, nullptr, DBC,
                     M, 40, 256, 256, 2, MTOK * 256, 256 * 40, MTOK * 40, 0);
        // 7. dt_raw = dbc[:, :8] @ dtw + dtb   [2][M][256]
        launch_sgemm(DBC, s_dtw + (long)l * 2 * 8 * 256, s_dtb + (long)l * 2 * 256, DT,
                     M, 256, 8, 40, 2, MTOK * 40, 8 * 256, MTOK * 256, 256);
        // 8. softplus
        softplus_kernel<<<EW2_BLOCKS, 256>>>(DT, EW2);
        // 9. selective scan -> Y [2][M][256]
        scan_kernel<<<512, 256>>>(DT, XC, DBC,
                                  s_alog + (long)l * 2 * 256 * 16,
                                  s_d + (long)l * 2 * 256, Y);
        // 10. y *= silu(z)
        ygate_kernel<<<EW2_BLOCKS, 256>>>(Y, XZ);
        // 11. so = y @ outw   [2][M][128]
        launch_sgemm(Y, s_outw + (long)l * 2 * 256 * 128, nullptr, SO,
                     M, 128, 256, 256, 2, MTOK * 256, 256 * 128, MTOK * 128, 0);
        // 12. concat + un-reverse -> CAT [M,256]
        concat_kernel<<<EW1_BLOCKS, 256>>>(SO, CAT);
        // 13. out = cat @ op_w + op_b   [M,256]
        launch_sgemm(CAT, op_w + (long)l * 256 * 256, op_b + l * 256, B256,
                     M, 256, 256, 256, 1, 0, 0, 0, 0);
        // 14. x = LN(res + out, ln2)
        ln_kernel<<<M, 256>>>(B256, X, ln2_g + l * 256, ln2_b + l * 256, X);
        // 15. ff = x @ w1 + b1   [M,1024]
        launch_sgemm(X, f_w1 + (long)l * 256 * 1024, f_b1 + l * 1024, FF,
                     M, 1024, 256, 256, 1, 0, 0, 0, 0);
        // 16. gelu
        gelu_kernel<<<(int)((MTOK * 1024 + 255) / 256), 256>>>(FF, MTOK * 1024);
        // 17. f = gelu @ w2 + b2 -> B256
        launch_sgemm(FF, f_w2 + (long)l * 1024 * 256, f_b2 + l * 256, B256,
                     M, 256, 1024, 1024, 1, 0, 0, 0, 0);
        // 18. x = LN(x + f, ln3)  (last layer writes d_out directly)
        float* dst = (l == 11) ? (float*)d_out : X;
        ln_kernel<<<M, 256>>>(B256, X, ln3_g + l * 256, ln3_b + l * 256, dst);
    }
}

// round 2
// speedup vs baseline: 1.8789x; 1.8789x over previous
#include <cuda_runtime.h>
#include <math.h>
#include <stdint.h>

// ---------------------------------------------------------------------------
// Problem constants
// ---------------------------------------------------------------------------
constexpr long MTOK  = 16 * 512;     // 8192 tokens

// ---------------------------------------------------------------------------
// Scratch arena (one __device__ global, allocation-free)
// ---------------------------------------------------------------------------
constexpr long OFF_X    = 0;
constexpr long OFF_LN   = OFF_X    + MTOK * 256;
constexpr long OFF_B256 = OFF_LN   + MTOK * 256;
constexpr long OFF_U    = OFF_B256 + MTOK * 256;
constexpr long OFF_XZ   = OFF_U    + 2 * MTOK * 128;
constexpr long OFF_XC   = OFF_XZ   + 2 * MTOK * 512;
constexpr long OFF_DBC  = OFF_XC   + 2 * MTOK * 256;
constexpr long OFF_DT   = OFF_DBC  + 2 * MTOK * 40;
constexpr long OFF_Y    = OFF_DT   + 2 * MTOK * 256;
constexpr long OFF_SO   = OFF_Y    + 2 * MTOK * 256;
constexpr long OFF_CAT  = OFF_SO   + 2 * MTOK * 128;
constexpr long OFF_FF   = OFF_CAT  + MTOK * 256;
constexpr long TOTAL_F  = OFF_FF   + MTOK * 1024;

__device__ float g_buf[TOTAL_F];

// ---------------------------------------------------------------------------
// Block-wide sum over 256 threads
// ---------------------------------------------------------------------------
__device__ __forceinline__ float blockSum256(float v, float* sbuf)
{
#pragma unroll
    for (int o = 16; o > 0; o >>= 1)
        v += __shfl_xor_sync(0xffffffffu, v, o);
    __syncthreads();
    if ((threadIdx.x & 31) == 0) sbuf[threadIdx.x >> 5] = v;
    __syncthreads();
    float s = sbuf[0];
#pragma unroll
    for (int i = 1; i < 8; i++) s += sbuf[i];
    return s;
}

// ---------------------------------------------------------------------------
// Embedding: x = LN(ids @ proj_w + proj_b)
// ---------------------------------------------------------------------------
__global__ void embed_ln_kernel(const float* __restrict__ ids,
                                const float* __restrict__ pw,
                                const float* __restrict__ pb,
                                const float* __restrict__ gam,
                                const float* __restrict__ bet,
                                float* __restrict__ x)
{
    __shared__ float sin[32];
    __shared__ float sred[8];
    int m = blockIdx.x, d = threadIdx.x;
    if (d < 32) sin[d] = ids[(long)m * 32 + d];
    __syncthreads();
    float v = pb[d];
#pragma unroll
    for (int e = 0; e < 32; e++)
        v = fmaf(sin[e], pw[e * 256 + d], v);
    float mean = blockSum256(v, sred) * (1.f / 256.f);
    float c = v - mean;
    float var = blockSum256(c * c, sred) * (1.f / 256.f);
    x[(long)m * 256 + d] = c * rsqrtf(var + 1e-5f) * gam[d] + bet[d];
}

// ---------------------------------------------------------------------------
// LayerNorm over D=256, optional residual add
// ---------------------------------------------------------------------------
__global__ void ln_kernel(const float* __restrict__ in,
                          const float* __restrict__ res,
                          const float* __restrict__ gam,
                          const float* __restrict__ bet,
                          float* __restrict__ out)
{
    __shared__ float sred[8];
    int m = blockIdx.x, d = threadIdx.x;
    float v = in[(long)m * 256 + d];
    if (res) v += res[(long)m * 256 + d];
    float mean = blockSum256(v, sred) * (1.f / 256.f);
    float c = v - mean;
    float var = blockSum256(c * c, sred) * (1.f / 256.f);
    out[(long)m * 256 + d] = c * rsqrtf(var + 1e-5f) * gam[d] + bet[d];
}

// ---------------------------------------------------------------------------
// TF32 tensor-core GEMM: C[g] = act(A[g] @ W[g] + bias)
// Requirements: M % 128 == 0, N % 128 == 0, K % 16 == 0, lda == K.
// Tile 128x128, BK=16, 8 warps, each warp 64x32 via mma.m16n8k8 tf32.
// act: 0 = none, 2 = exact GELU
// ---------------------------------------------------------------------------
__global__ void __launch_bounds__(256)
tf32gemm_kernel(const float* __restrict__ A,
                const float* __restrict__ W,
                const float* __restrict__ bias,
                float* __restrict__ C,
                int M, int N, int K, int act,
                long sAg, long sWg, long sCg)
{
    int g = blockIdx.z;
    A += (long)g * sAg;
    W += (long)g * sWg;
    C += (long)g * sCg;

    __shared__ uint32_t As[128][20];   // [m][k], pad 16->20 (conflict-free)
    __shared__ uint32_t Bs[16][136];   // [k][n], pad 128->136 (conflict-free)

    int tid  = threadIdx.x;
    int warp = tid >> 5;
    int lane = tid & 31;
    int wm = (warp & 1) * 64;          // warp m-offset within tile
    int wn = (warp >> 1) * 32;         // warp n-offset within tile
    int gID = lane >> 2;               // 0..7
    int tig = lane & 3;                // 0..3
    int rowBase = blockIdx.y * 128;
    int colBase = blockIdx.x * 128;

    float acc[4][4][4];
#pragma unroll
    for (int a = 0; a < 4; a++)
#pragma unroll
        for (int b = 0; b < 4; b++)
#pragma unroll
            for (int c = 0; c < 4; c++) acc[a][b][c] = 0.f;

    for (int k0 = 0; k0 < K; k0 += 16) {
        // stage A tile 128x16 (cvt fp32 -> tf32)
#pragma unroll
        for (int it = 0; it < 2; it++) {
            int f = tid + it * 256;            // 0..511
            int r = f >> 2;
            int k4 = (f & 3) * 4;
            float4 v = *(const float4*)&A[(long)(rowBase + r) * K + k0 + k4];
            uint4 u;
            asm("cvt.rna.tf32.f32 %0, %1;" : "=r"(u.x) : "f"(v.x));
            asm("cvt.rna.tf32.f32 %0, %1;" : "=r"(u.y) : "f"(v.y));
            asm("cvt.rna.tf32.f32 %0, %1;" : "=r"(u.z) : "f"(v.z));
            asm("cvt.rna.tf32.f32 %0, %1;" : "=r"(u.w) : "f"(v.w));
            *(uint4*)&As[r][k4] = u;
        }
        // stage B tile 16x128
#pragma unroll
        for (int it = 0; it < 2; it++) {
            int f = tid + it * 256;
            int kr = f >> 5;
            int n4 = (f & 31) * 4;
            float4 v = *(const float4*)&W[(long)(k0 + kr) * N + colBase + n4];
            uint4 u;
            asm("cvt.rna.tf32.f32 %0, %1;" : "=r"(u.x) : "f"(v.x));
            asm("cvt.rna.tf32.f32 %0, %1;" : "=r"(u.y) : "f"(v.y));
            asm("cvt.rna.tf32.f32 %0, %1;" : "=r"(u.z) : "f"(v.z));
            asm("cvt.rna.tf32.f32 %0, %1;" : "=r"(u.w) : "f"(v.w));
            *(uint4*)&Bs[kr][n4] = u;
        }
        __syncthreads();

#pragma unroll
        for (int ks = 0; ks < 16; ks += 8) {
            uint32_t bf[4][2];
#pragma unroll
            for (int nt = 0; nt < 4; nt++) {
                int col = wn + nt * 8 + gID;
                bf[nt][0] = Bs[ks + tig][col];
                bf[nt][1] = Bs[ks + tig + 4][col];
            }
#pragma unroll
            for (int mt = 0; mt < 4; mt++) {
                int row = wm + mt * 16 + gID;
                uint32_t a0 = As[row][ks + tig];
                uint32_t a1 = As[row + 8][ks + tig];
                uint32_t a2 = As[row][ks + tig + 4];
                uint32_t a3 = As[row + 8][ks + tig + 4];
#pragma unroll
                for (int nt = 0; nt < 4; nt++) {
                    asm volatile(
                        "mma.sync.aligned.m16n8k8.row.col.f32.tf32.tf32.f32 "
                        "{%0,%1,%2,%3}, {%4,%5,%6,%7}, {%8,%9}, {%0,%1,%2,%3};\n"
                        : "+f"(acc[mt][nt][0]), "+f"(acc[mt][nt][1]),
                          "+f"(acc[mt][nt][2]), "+f"(acc[mt][nt][3])
                        : "r"(a0), "r"(a1), "r"(a2), "r"(a3),
                          "r"(bf[nt][0]), "r"(bf[nt][1]));
                }
            }
        }
        __syncthreads();
    }

    // epilogue: bias + optional gelu, float2 stores
#pragma unroll
    for (int mt = 0; mt < 4; mt++) {
        int row0 = rowBase + wm + mt * 16 + gID;
#pragma unroll
        for (int nt = 0; nt < 4; nt++) {
            int col = colBase + wn + nt * 8 + tig * 2;
            float b0 = 0.f, b1 = 0.f;
            if (bias) { b0 = bias[col]; b1 = bias[col + 1]; }
            float v00 = acc[mt][nt][0] + b0;
            float v01 = acc[mt][nt][1] + b1;
            float v10 = acc[mt][nt][2] + b0;
            float v11 = acc[mt][nt][3] + b1;
            if (act == 2) {
                v00 = 0.5f * v00 * (1.f + erff(v00 * 0.70710678118654752f));
                v01 = 0.5f * v01 * (1.f + erff(v01 * 0.70710678118654752f));
                v10 = 0.5f * v10 * (1.f + erff(v10 * 0.70710678118654752f));
                v11 = 0.5f * v11 * (1.f + erff(v11 * 0.70710678118654752f));
            }
            float2 lo = make_float2(v00, v01);
            float2 hi = make_float2(v10, v11);
            *(float2*)&C[(long)row0 * N + col] = lo;
            *(float2*)&C[(long)(row0 + 8) * N + col] = hi;
        }
    }
}

// ---------------------------------------------------------------------------
// fp32 fallback SGEMM (small N / small K GEMMs): C = act(A @ W + bias)
// act: 0 = none, 1 = softplus
// ---------------------------------------------------------------------------
__global__ void sgemm_kernel(const float* __restrict__ A,
                             const float* __restrict__ W,
                             const float* __restrict__ bias,
                             float* __restrict__ C,
                             int M, int N, int K, int lda, int act,
                             long sAg, long sWg, long sCg, long sBg)
{
    int g = blockIdx.z;
    A += (long)g * sAg;
    W += (long)g * sWg;
    C += (long)g * sCg;
    if (bias) bias += (long)g * sBg;

    __shared__ __align__(16) float As[16][128];
    __shared__ __align__(16) float Ws[16][64];

    int tid = threadIdx.x;
    int tx = tid & 15;
    int ty = tid >> 4;
    int rowBase = blockIdx.y * 128;
    int colBase = blockIdx.x * 64;

    float acc[8][4];
#pragma unroll
    for (int i = 0; i < 8; i++)
#pragma unroll
        for (int j = 0; j < 4; j++) acc[i][j] = 0.f;

    for (int k0 = 0; k0 < K; k0 += 16) {
#pragma unroll
        for (int it = 0; it < 8; it++) {
            int idx = tid + it * 256;
            int m = idx >> 4;
            int kk = idx & 15;
            int gr = rowBase + m, gk = k0 + kk;
            As[kk][m] = (gr < M && gk < K) ? A[(long)gr * lda + gk] : 0.f;
        }
#pragma unroll
        for (int it = 0; it < 4; it++) {
            int idx = tid + it * 256;
            int kk = idx >> 6;
            int n = idx & 63;
            int gk = k0 + kk, gn = colBase + n;
            Ws[kk][n] = (gk < K && gn < N) ? W[(long)gk * N + gn] : 0.f;
        }
        __syncthreads();
#pragma unroll
        for (int k = 0; k < 16; k++) {
            float a[8], w[4];
            float4 a0 = *(const float4*)&As[k][ty * 8];
            float4 a1 = *(const float4*)&As[k][ty * 8 + 4];
            a[0] = a0.x; a[1] = a0.y; a[2] = a0.z; a[3] = a0.w;
            a[4] = a1.x; a[5] = a1.y; a[6] = a1.z; a[7] = a1.w;
            float4 w0 = *(const float4*)&Ws[k][tx * 4];
            w[0] = w0.x; w[1] = w0.y; w[2] = w0.z; w[3] = w0.w;
#pragma unroll
            for (int i = 0; i < 8; i++)
#pragma unroll
                for (int j = 0; j < 4; j++)
                    acc[i][j] = fmaf(a[i], w[j], acc[i][j]);
        }
        __syncthreads();
    }

#pragma unroll
    for (int i = 0; i < 8; i++) {
        int gr = rowBase + ty * 8 + i;
        if (gr >= M) continue;
#pragma unroll
        for (int j = 0; j < 4; j++) {
            int gn = colBase + tx * 4 + j;
            if (gn >= N) continue;
            float v = acc[i][j];
            if (bias) v += bias[gn];
            if (act == 1) v = (v > 20.f) ? v : log1pf(expf(v));
            C[(long)gr * N + gn] = v;
        }
    }
}

// ---------------------------------------------------------------------------
// split + reverse
// ---------------------------------------------------------------------------
__global__ void splitrev_kernel(const float* __restrict__ h, float* __restrict__ u)
{
    long i = (long)blockIdx.x * 256 + threadIdx.x;
    if (i >= MTOK * 256) return;
    long m = i >> 8;
    int j = (int)(i & 255);
    float v = h[i];
    if (j < 128) {
        u[m * 128 + j] = v;
    } else {
        long b = m >> 9;
        long t = m & 511;
        u[MTOK * 128 + ((b << 9) + 511 - t) * 128 + (j - 128)] = v;
    }
}

// ---------------------------------------------------------------------------
// depthwise causal conv (K=4) + bias + silu
// ---------------------------------------------------------------------------
__global__ void conv_silu_kernel(const float* __restrict__ xz,
                                 const float* __restrict__ convw,
                                 const float* __restrict__ convb,
                                 float* __restrict__ xc)
{
    long i = (long)blockIdx.x * 256 + threadIdx.x;
    if (i >= 2 * MTOK * 256) return;
    int d = (int)(i & 255);
    long gm = i >> 8;
    int g = (int)(gm / MTOK);
    long m = gm % MTOK;
    int t = (int)(m & 511);

    const float* w = convw + ((long)g * 256 + d) * 4;
    const float* xp = xz + ((long)g * MTOK + m) * 512 + d;
    float acc = convb[(long)g * 256 + d];
#pragma unroll
    for (int k = 0; k < 4; k++) {
        int tt = t - 3 + k;
        if (tt >= 0) acc = fmaf(xp[(long)(k - 3) * 512], w[k], acc);
    }
    xc[i] = acc / (1.f + expf(-acc));
}

// ---------------------------------------------------------------------------
// Selective scan: 16-lane group per (g, b, d); lane = n
// ---------------------------------------------------------------------------
__global__ void scan_kernel(const float* __restrict__ dt,
                            const float* __restrict__ xc,
                            const float* __restrict__ dbc,
                            const float* __restrict__ alog,
                            const float* __restrict__ dpar,
                            float* __restrict__ y)
{
    int grp = blockIdx.x * 16 + (threadIdx.x >> 4);
    int n = threadIdx.x & 15;
    int g = grp >> 12;
    int bd = grp & 4095;
    int b = bd >> 8;
    int d = bd & 255;

    float A = -expf(alog[((long)(g * 256 + d)) * 16 + n]);
    float dp = dpar[(long)g * 256 + d];

    long mbase = (long)g * MTOK + (long)b * 512;
    const float* dtp = dt + mbase * 256 + d;
    const float* xcp = xc + mbase * 256 + d;
    const float* dbp = dbc + mbase * 40;
    float* yp = y + mbase * 256 + d;

    float h = 0.f;
    for (int t = 0; t < 512; t++) {
        float dtv = dtp[(long)t * 256];
        float xv = xcp[(long)t * 256];
        float Bn = dbp[(long)t * 40 + 8 + n];
        float Cn = dbp[(long)t * 40 + 24 + n];
        h = expf(dtv * A) * h + dtv * Bn * xv;
        float p = h * Cn;
        p += __shfl_xor_sync(0xffffffffu, p, 8);
        p += __shfl_xor_sync(0xffffffffu, p, 4);
        p += __shfl_xor_sync(0xffffffffu, p, 2);
        p += __shfl_xor_sync(0xffffffffu, p, 1);
        if (n == 0) yp[(long)t * 256] = p + dp * xv;
    }
}

// ---------------------------------------------------------------------------
// y *= silu(z)
// ---------------------------------------------------------------------------
__global__ void ygate_kernel(float* __restrict__ y, const float* __restrict__ xz)
{
    long i = (long)blockIdx.x * 256 + threadIdx.x;
    if (i >= 2 * MTOK * 256) return;
    int d = (int)(i & 255);
    long gm = i >> 8;
    float z = xz[gm * 512 + 256 + d];
    y[i] *= z / (1.f + expf(-z));
}

// ---------------------------------------------------------------------------
// concat + un-reverse
// ---------------------------------------------------------------------------
__global__ void concat_kernel(const float* __restrict__ so, float* __restrict__ cat)
{
    long i = (long)blockIdx.x * 256 + threadIdx.x;
    if (i >= MTOK * 256) return;
    long m = i >> 8;
    int j = (int)(i & 255);
    float v;
    if (j < 128) {
        v = so[m * 128 + j];
    } else {
        long b = m >> 9;
        long t = m & 511;
        v = so[MTOK * 128 + ((b << 9) + 511 - t) * 128 + (j - 128)];
    }
    cat[i] = v;
}

// ---------------------------------------------------------------------------
// Launch helpers
// ---------------------------------------------------------------------------
static void launch_tf32(const float* A, const float* W, const float* bias, float* C,
                        int M, int N, int K, int act, int G,
                        long sAg, long sWg, long sCg)
{
    dim3 grid(N / 128, M / 128, G);
    tf32gemm_kernel<<<grid, 256>>>(A, W, bias, C, M, N, K, act, sAg, sWg, sCg);
}

static void launch_sgemm(const float* A, const float* W, const float* bias, float* C,
                         int M, int N, int K, int lda, int act, int G,
                         long sAg, long sWg, long sCg, long sBg)
{
    dim3 grid((N + 63) / 64, (M + 127) / 128, G);
    sgemm_kernel<<<grid, 256>>>(A, W, bias, C, M, N, K, lda, act, sAg, sWg, sCg, sBg);
}

extern "C" void kernel_launch(void* const* d_in, const int* in_sizes, int n_in,
                              void* d_out, int out_size)
{
    const float* input_ids = (const float*)d_in[0];
    const float* proj_w    = (const float*)d_in[1];
    const float* proj_b    = (const float*)d_in[2];
    const float* ln0_g     = (const float*)d_in[3];
    const float* ln0_b     = (const float*)d_in[4];
    const float* ln1_g     = (const float*)d_in[5];
    const float* ln1_b     = (const float*)d_in[6];
    const float* ip_w      = (const float*)d_in[7];
    const float* ip_b      = (const float*)d_in[8];
    const float* s_inw     = (const float*)d_in[9];
    const float* s_convw   = (const float*)d_in[10];
    const float* s_convb   = (const float*)d_in[11];
    const float* s_xw      = (const float*)d_in[12];
    const float* s_dtw     = (const float*)d_in[13];
    const float* s_dtb     = (const float*)d_in[14];
    const float* s_alog    = (const float*)d_in[15];
    const float* s_d       = (const float*)d_in[16];
    const float* s_outw    = (const float*)d_in[17];
    const float* op_w      = (const float*)d_in[18];
    const float* op_b      = (const float*)d_in[19];
    const float* ln2_g     = (const float*)d_in[20];
    const float* ln2_b     = (const float*)d_in[21];
    const float* f_w1      = (const float*)d_in[22];
    const float* f_b1      = (const float*)d_in[23];
    const float* f_w2      = (const float*)d_in[24];
    const float* f_b2      = (const float*)d_in[25];
    const float* ln3_g     = (const float*)d_in[26];
    const float* ln3_b     = (const float*)d_in[27];

    float* base = nullptr;
    cudaGetSymbolAddress((void**)&base, g_buf);

    float* X    = base + OFF_X;
    float* LNb  = base + OFF_LN;
    float* B256 = base + OFF_B256;
    float* U    = base + OFF_U;
    float* XZ   = base + OFF_XZ;
    float* XC   = base + OFF_XC;
    float* DBC  = base + OFF_DBC;
    float* DT   = base + OFF_DT;
    float* Y    = base + OFF_Y;
    float* SO   = base + OFF_SO;
    float* CAT  = base + OFF_CAT;
    float* FF   = base + OFF_FF;

    const int M = (int)MTOK;
    const long EW2 = 2 * MTOK * 256;
    const int EW2_BLOCKS = (int)((EW2 + 255) / 256);
    const int EW1_BLOCKS = (int)((MTOK * 256 + 255) / 256);

    embed_ln_kernel<<<M, 256>>>(input_ids, proj_w, proj_b, ln0_g, ln0_b, X);

    for (int l = 0; l < 12; l++) {
        // LN1
        ln_kernel<<<M, 256>>>(X, nullptr, ln1_g + l * 256, ln1_b + l * 256, LNb);
        // in-proj (tf32): [M,256] = LN @ [256,256] + b
        launch_tf32(LNb, ip_w + (long)l * 256 * 256, ip_b + l * 256, B256,
                    M, 256, 256, 0, 1, 0, 0, 0);
        // split + reverse
        splitrev_kernel<<<EW1_BLOCKS, 256>>>(B256, U);
        // xz = u @ inw (tf32, batched 2): [2][M,512] = [2][M,128] @ [2][128,512]
        launch_tf32(U, s_inw + (long)l * 2 * 128 * 512, nullptr, XZ,
                    M, 512, 128, 0, 2, MTOK * 128, 128 * 512, MTOK * 512);
        // conv + silu
        conv_silu_kernel<<<EW2_BLOCKS, 256>>>(XZ, s_convw + (long)l * 2 * 256 * 4,
                                              s_convb + (long)l * 2 * 256, XC);
        // dbc = xc @ xw (fp32, N=40)
        launch_sgemm(XC, s_xw + (long)l * 2 * 256 * 40, nullptr, DBC,
                     M, 40, 256, 256, 0, 2, MTOK * 256, 256 * 40, MTOK * 40, 0);
        // dt = softplus(dbc[:, :8] @ dtw + dtb)  (fp32, K=8, fused softplus)
        launch_sgemm(DBC, s_dtw + (long)l * 2 * 8 * 256, s_dtb + (long)l * 2 * 256, DT,
                     M, 256, 8, 40, 1, 2, MTOK * 40, 8 * 256, MTOK * 256, 256);
        // selective scan
        scan_kernel<<<512, 256>>>(DT, XC, DBC,
                                  s_alog + (long)l * 2 * 256 * 16,
                                  s_d + (long)l * 2 * 256, Y);
        // gate
        ygate_kernel<<<EW2_BLOCKS, 256>>>(Y, XZ);
        // so = y @ outw (tf32, batched 2): [2][M,128]
        launch_tf32(Y, s_outw + (long)l * 2 * 256 * 128, nullptr, SO,
                    M, 128, 256, 0, 2, MTOK * 256, 256 * 128, MTOK * 128);
        // concat + un-reverse
        concat_kernel<<<EW1_BLOCKS, 256>>>(SO, CAT);
        // out-proj (tf32)
        launch_tf32(CAT, op_w + (long)l * 256 * 256, op_b + l * 256, B256,
                    M, 256, 256, 0, 1, 0, 0, 0);
        // LN2 (residual)
        ln_kernel<<<M, 256>>>(B256, X, ln2_g + l * 256, ln2_b + l * 256, X);
        // ff = gelu(x @ w1 + b1) (tf32, fused gelu)
        launch_tf32(X, f_w1 + (long)l * 256 * 1024, f_b1 + l * 1024, FF,
                    M, 1024, 256, 2, 1, 0, 0, 0);
        // f = ff @ w2 + b2 (tf32)
        launch_tf32(FF, f_w2 + (long)l * 1024 * 256, f_b2 + l * 256, B256,
                    M, 256, 1024, 0, 1, 0, 0, 0);
        // LN3 (residual); last layer -> d_out
        float* dst = (l == 11) ? (float*)d_out : X;
        ln_kernel<<<M, 256>>>(B256, X, ln3_g + l * 256, ln3_b + l * 256, dst);
    }
}